// round 5
// baseline (speedup 1.0000x reference)
#include <cuda_runtime.h>

#define N_NODES   1000000
#define N_EDGES   2000000
#define N_FEAT    11
#define FPAD      12          // padded feature stride (16B-aligned rows); slot 11 = dinv
#define HIDDEN    64
#define N_CLASSES 19
#define BATCH     128

#define SPLIT 8      // blocks per batch segment in transform_pool
#define TILE  128    // nodes staged per smem tile

// ---- scratch (no allocs allowed; device globals) ----
__device__ float g_deg[N_NODES];
__device__ float g_dinv[N_NODES];
__device__ __align__(16) float g_xpad[N_NODES * FPAD];   // 48 MB: u = x * dinv[row], slot11 = dinv
__device__ __align__(16) float g_aggx[N_NODES * FPAD];   // 48 MB unnormalized agg of u
__device__ float g_pooled[BATCH * HIDDEN];
__device__ int   g_bnd[BATCH + 1];

__device__ __forceinline__ void red_add_v4(float* addr, float a, float b, float c, float d) {
    asm volatile("red.global.add.v4.f32 [%0], {%1,%2,%3,%4};"
                 :: "l"(addr), "f"(a), "f"(b), "f"(c), "f"(d) : "memory");
}

// deg[c] += 1 per incoming edge; 4 edges/thread via int4.
__global__ void deg_kernel(const int* __restrict__ ei) {
    int q = blockIdx.x * blockDim.x + threadIdx.x;
    if (q >= N_EDGES / 4) return;
    int4 cc = ((const int4*)(ei + N_EDGES))[q];
    if ((unsigned)cc.x < N_NODES) atomicAdd(&g_deg[cc.x], 1.0f);
    if ((unsigned)cc.y < N_NODES) atomicAdd(&g_deg[cc.y], 1.0f);
    if ((unsigned)cc.z < N_NODES) atomicAdd(&g_deg[cc.z], 1.0f);
    if ((unsigned)cc.w < N_NODES) atomicAdd(&g_deg[cc.w], 1.0f);
}

__global__ void dinv_kernel() {
    int n = blockIdx.x * blockDim.x + threadIdx.x;
    if (n < N_NODES) {
        float d = g_deg[n];
        g_dinv[n] = (d > 0.0f) ? rsqrtf(d) : 0.0f;
    }
}

// Build u[n][f] = x[n][f] * dinv[n] (f<11), u[n][11] = dinv[n].
__global__ void pad_kernel(const float* __restrict__ x) {
    int i = blockIdx.x * blockDim.x + threadIdx.x;
    const int total = N_NODES * FPAD;
    for (; i < total; i += gridDim.x * blockDim.x) {
        int n = i / FPAD, f = i - n * FPAD;
        float dv = g_dinv[n];
        g_xpad[i] = (f < N_FEAT) ? x[n * N_FEAT + f] * dv : dv;
    }
}

// Edge aggregation (unnormalized-by-target): aggx[c] += u[r].
// 4 edges/thread: 2x LDG.128 idx + per edge 3x LDG.128 + up to 3x red.v4.
__global__ void __launch_bounds__(256)
edge_agg_kernel(const int* __restrict__ ei) {
    int q = blockIdx.x * blockDim.x + threadIdx.x;
    if (q >= N_EDGES / 4) return;
    int4 rr = ((const int4*)ei)[q];
    int4 cc = ((const int4*)(ei + N_EDGES))[q];

    #pragma unroll
    for (int k = 0; k < 4; k++) {
        int r = (k == 0) ? rr.x : (k == 1) ? rr.y : (k == 2) ? rr.z : rr.w;
        int c = (k == 0) ? cc.x : (k == 1) ? cc.y : (k == 2) ? cc.z : cc.w;
        if ((unsigned)r >= N_NODES || (unsigned)c >= N_NODES) continue;
        const float4* ur = (const float4*)&g_xpad[r * FPAD];
        float4 v0 = ur[0], v1 = ur[1], v2 = ur[2];
        if (v2.w == 0.0f) continue;   // dinv[r]==0 -> u row is all zeros
        float* dst = &g_aggx[c * FPAD];
        red_add_v4(dst + 0, v0.x, v0.y, v0.z, v0.w);
        red_add_v4(dst + 4, v1.x, v1.y, v1.z, v1.w);
        red_add_v4(dst + 8, v2.x, v2.y, v2.z, 0.0f);
    }
}

// Segment boundaries of sorted batch ids, vectorized: bnd[k] = first i with batch[i] >= k
__global__ void bnd_kernel(const int* __restrict__ batch) {
    int q = blockIdx.x * blockDim.x + threadIdx.x;
    if (q >= N_NODES / 4) return;
    int i0 = q * 4;
    int4 v = ((const int4*)batch)[q];
    int prev = (i0 == 0) ? -1 : batch[i0 - 1];
    int vals[4] = {v.x, v.y, v.z, v.w};
    #pragma unroll
    for (int t = 0; t < 4; t++) {
        int cur = vals[t];
        for (int k = prev + 1; k <= cur && k <= BATCH; k++) g_bnd[k] = i0 + t;
        prev = cur;
    }
    if (i0 + 4 == N_NODES) {
        for (int k = prev + 1; k <= BATCH; k++) g_bnd[k] = N_NODES;
    }
}

// Fused post-scale (dinv[c]) + transform + ReLU + pooling-sum.
// Block = 256 threads = 4 node-strides x 64 features; float4 LDS inner loop.
__global__ void __launch_bounds__(256, 4)
transform_pool_kernel(const float* __restrict__ Wc,
                      const float* __restrict__ bc) {
    int b     = blockIdx.x / SPLIT;
    int split = blockIdx.x % SPLIT;
    int start = g_bnd[b];
    int end   = g_bnd[b + 1];
    int total = end - start;
    int chunk = (total + SPLIT - 1) / SPLIT;
    int s0    = start + split * chunk;
    int s1    = min(s0 + chunk, end);

    __shared__ float sW[N_FEAT * HIDDEN];
    __shared__ float sb[HIDDEN];
    __shared__ __align__(16) float sx[TILE][FPAD];
    __shared__ float sdinv[TILE];
    __shared__ float red[4][HIDDEN];

    for (int i = threadIdx.x; i < N_FEAT * HIDDEN; i += blockDim.x) sW[i] = Wc[i];
    if (threadIdx.x < HIDDEN) sb[threadIdx.x] = bc[threadIdx.x];
    __syncthreads();

    int j = threadIdx.x & 63;   // hidden feature
    int s = threadIdx.x >> 6;   // node-stride group 0..3

    float w0 = sW[0*HIDDEN+j], w1 = sW[1*HIDDEN+j], w2 = sW[2*HIDDEN+j], w3 = sW[3*HIDDEN+j];
    float w4 = sW[4*HIDDEN+j], w5 = sW[5*HIDDEN+j], w6 = sW[6*HIDDEN+j], w7 = sW[7*HIDDEN+j];
    float w8 = sW[8*HIDDEN+j], w9 = sW[9*HIDDEN+j], w10 = sW[10*HIDDEN+j];
    float bj  = sb[j];
    float acc = 0.0f;

    for (int t0 = s0; t0 < s1; t0 += TILE) {
        int cnt = min(TILE, s1 - t0);
        __syncthreads();
        {
            float4*       sx4 = (float4*)&sx[0][0];
            const float4* src = (const float4*)&g_aggx[(long long)t0 * FPAD];
            int nv = cnt * (FPAD / 4);
            for (int i = threadIdx.x; i < nv; i += blockDim.x) sx4[i] = src[i];
            for (int i = threadIdx.x; i < cnt; i += blockDim.x) sdinv[i] = g_dinv[t0 + i];
        }
        __syncthreads();
        for (int n = s; n < cnt; n += 4) {
            float4 a = *(const float4*)&sx[n][0];
            float4 d4 = *(const float4*)&sx[n][4];
            float4 c4 = *(const float4*)&sx[n][8];
            float dot = a.x * w0;
            dot = fmaf(a.y,  w1,  dot);
            dot = fmaf(a.z,  w2,  dot);
            dot = fmaf(a.w,  w3,  dot);
            dot = fmaf(d4.x, w4,  dot);
            dot = fmaf(d4.y, w5,  dot);
            dot = fmaf(d4.z, w6,  dot);
            dot = fmaf(d4.w, w7,  dot);
            dot = fmaf(c4.x, w8,  dot);
            dot = fmaf(c4.y, w9,  dot);
            dot = fmaf(c4.z, w10, dot);
            float h = fmaf(dot, sdinv[n], bj);   // post-scale by dinv[target] + bias
            acc += fmaxf(h, 0.0f);
        }
    }

    red[s][j] = acc;
    __syncthreads();
    if (s == 0) {
        float tot = red[0][j] + red[1][j] + red[2][j] + red[3][j];
        atomicAdd(&g_pooled[b * HIDDEN + j], tot);
    }
}

// out[b][c] = (pooled[b]/max(cnt,1)) @ W_lin + b_lin
__global__ void final_kernel(const float* __restrict__ Wlin,
                             const float* __restrict__ blin,
                             float* __restrict__ out) {
    int t = blockIdx.x * blockDim.x + threadIdx.x;
    if (t < BATCH * N_CLASSES) {
        int b = t / N_CLASSES, c = t % N_CLASSES;
        int cnt   = g_bnd[b + 1] - g_bnd[b];
        float inv = 1.0f / fmaxf((float)cnt, 1.0f);
        float acc = blin[c];
        #pragma unroll 8
        for (int jj = 0; jj < HIDDEN; jj++)
            acc = fmaf(g_pooled[b * HIDDEN + jj] * inv, Wlin[jj * N_CLASSES + c], acc);
        out[t] = acc;
    }
}

extern "C" void kernel_launch(void* const* d_in, const int* in_sizes, int n_in,
                              void* d_out, int out_size) {
    const float* x     = (const float*)d_in[0];
    const int*   ei    = (const int*)d_in[1];     // int64 narrowed to int32 by harness
    // d_in[2] = y (unused)
    const int*   batch = (const int*)d_in[3];     // int64 narrowed to int32 by harness
    const float* Wc    = (const float*)d_in[4];
    const float* bc    = (const float*)d_in[5];
    const float* Wlin  = (const float*)d_in[6];
    const float* blin  = (const float*)d_in[7];
    float*       out   = (float*)d_out;

    // Symbol addresses cached on the (uncaptured) correctness call.
    static void* p_deg    = nullptr;
    static void* p_aggx   = nullptr;
    static void* p_pooled = nullptr;
    if (!p_deg) {
        cudaGetSymbolAddress(&p_deg,    g_deg);
        cudaGetSymbolAddress(&p_aggx,   g_aggx);
        cudaGetSymbolAddress(&p_pooled, g_pooled);
    }

    cudaMemsetAsync(p_deg,    0, sizeof(float) * N_NODES);
    cudaMemsetAsync(p_aggx,   0, sizeof(float) * N_NODES * FPAD);
    cudaMemsetAsync(p_pooled, 0, sizeof(float) * BATCH * HIDDEN);

    deg_kernel<<<(N_EDGES / 4 + 255) / 256, 256>>>(ei);
    dinv_kernel<<<(N_NODES + 255) / 256, 256>>>();
    pad_kernel<<<2048, 256>>>(x);
    bnd_kernel<<<(N_NODES / 4 + 255) / 256, 256>>>(batch);
    edge_agg_kernel<<<(N_EDGES / 4 + 255) / 256, 256>>>(ei);
    transform_pool_kernel<<<BATCH * SPLIT, 256>>>(Wc, bc);
    final_kernel<<<(BATCH * N_CLASSES + 127) / 128, 128>>>(Wlin, blin, out);
}

// round 6
// speedup vs baseline: 1.0573x; 1.0573x over previous
#include <cuda_runtime.h>

#define N_NODES   1000000
#define N_EDGES   2000000
#define N_FEAT    11
#define FPAD      12
#define HIDDEN    64
#define N_CLASSES 19
#define BATCH     128

#define SPLIT 16      // blocks per batch segment in fused kernel
#define TILE  256     // nodes per smem tile
#define SCAN_B 1024
#define NB_SCAN ((N_NODES + SCAN_B - 1) / SCAN_B)   // 977

// ---- scratch (device globals; no allocs) ----
__device__ int   g_count[N_NODES];        // in-degree (int)
__device__ int   g_rowptr[N_NODES + 1];   // CSR offsets
__device__ int   g_cursor[N_NODES];       // fill cursors
__device__ int   g_srcs[N_EDGES];         // CSR source ids
__device__ float g_dinv[N_NODES];
__device__ __align__(16) float g_xpad[N_NODES * FPAD];  // u = x * dinv[row]
__device__ float g_pooled[BATCH * HIDDEN];
__device__ int   g_bnd[BATCH + 1];
__device__ int   g_bsum[NB_SCAN];
__device__ int   g_boffs[NB_SCAN];

// ---- histogram over targets (this is also deg) ----
__global__ void hist_kernel(const int* __restrict__ ei) {
    int q = blockIdx.x * blockDim.x + threadIdx.x;
    if (q >= N_EDGES / 4) return;
    int4 cc = ((const int4*)(ei + N_EDGES))[q];
    if ((unsigned)cc.x < N_NODES) atomicAdd(&g_count[cc.x], 1);
    if ((unsigned)cc.y < N_NODES) atomicAdd(&g_count[cc.y], 1);
    if ((unsigned)cc.z < N_NODES) atomicAdd(&g_count[cc.z], 1);
    if ((unsigned)cc.w < N_NODES) atomicAdd(&g_count[cc.w], 1);
}

// ---- 3-phase exclusive scan of g_count -> g_rowptr ----
__global__ void scan1_kernel() {
    __shared__ int sd[SCAN_B];
    int tid = threadIdx.x;
    int i = blockIdx.x * SCAN_B + tid;
    int v = (i < N_NODES) ? g_count[i] : 0;
    sd[tid] = v;
    __syncthreads();
    for (int off = 1; off < SCAN_B; off <<= 1) {
        int t = (tid >= off) ? sd[tid - off] : 0;
        __syncthreads();
        sd[tid] += t;
        __syncthreads();
    }
    if (i < N_NODES) g_rowptr[i] = sd[tid] - v;   // block-local exclusive
    if (tid == SCAN_B - 1) g_bsum[blockIdx.x] = sd[tid];
}

__global__ void scan2_kernel() {
    __shared__ int sd[SCAN_B];
    int tid = threadIdx.x;
    int v = (tid < NB_SCAN) ? g_bsum[tid] : 0;
    sd[tid] = v;
    __syncthreads();
    for (int off = 1; off < SCAN_B; off <<= 1) {
        int t = (tid >= off) ? sd[tid - off] : 0;
        __syncthreads();
        sd[tid] += t;
        __syncthreads();
    }
    if (tid < NB_SCAN) g_boffs[tid] = sd[tid] - v;
    if (tid == SCAN_B - 1) g_rowptr[N_NODES] = sd[tid];   // total edges
}

__global__ void scan3_kernel() {
    int i = blockIdx.x * blockDim.x + threadIdx.x;
    if (i < N_NODES) {
        int val = g_rowptr[i] + g_boffs[i >> 10];
        g_rowptr[i] = val;
        g_cursor[i] = val;
    }
}

__global__ void dinv_kernel() {
    int n = blockIdx.x * blockDim.x + threadIdx.x;
    if (n < N_NODES) {
        int d = g_count[n];
        g_dinv[n] = (d > 0) ? rsqrtf((float)d) : 0.0f;
    }
}

// u[n][f] = x[n][f] * dinv[n]; slot 11 = dinv[n]
__global__ void pad_kernel(const float* __restrict__ x) {
    int i = blockIdx.x * blockDim.x + threadIdx.x;
    const int total = N_NODES * FPAD;
    for (; i < total; i += gridDim.x * blockDim.x) {
        int n = i / FPAD, f = i - n * FPAD;
        float dv = g_dinv[n];
        g_xpad[i] = (f < N_FEAT) ? x[n * N_FEAT + f] * dv : dv;
    }
}

// CSR fill: srcs[slot] = source id, grouped by target
__global__ void fill_kernel(const int* __restrict__ ei) {
    int q = blockIdx.x * blockDim.x + threadIdx.x;
    if (q >= N_EDGES / 4) return;
    int4 rr = ((const int4*)ei)[q];
    int4 cc = ((const int4*)(ei + N_EDGES))[q];
    #pragma unroll
    for (int k = 0; k < 4; k++) {
        int r = (k == 0) ? rr.x : (k == 1) ? rr.y : (k == 2) ? rr.z : rr.w;
        int c = (k == 0) ? cc.x : (k == 1) ? cc.y : (k == 2) ? cc.z : cc.w;
        if ((unsigned)c < N_NODES) {
            int pos = atomicAdd(&g_cursor[c], 1);
            if ((unsigned)pos < N_EDGES) g_srcs[pos] = r;
        }
    }
}

// Segment boundaries of sorted batch ids
__global__ void bnd_kernel(const int* __restrict__ batch) {
    int q = blockIdx.x * blockDim.x + threadIdx.x;
    if (q >= N_NODES / 4) return;
    int i0 = q * 4;
    int4 v = ((const int4*)batch)[q];
    int prev = (i0 == 0) ? -1 : batch[i0 - 1];
    int vals[4] = {v.x, v.y, v.z, v.w};
    #pragma unroll
    for (int t = 0; t < 4; t++) {
        int cur = vals[t];
        for (int k = prev + 1; k <= cur && k <= BATCH; k++) g_bnd[k] = i0 + t;
        prev = cur;
    }
    if (i0 + 4 == N_NODES) {
        for (int k = prev + 1; k <= BATCH; k++) g_bnd[k] = N_NODES;
    }
}

// Fused CSR-gather + aggregate + scale + transform + ReLU + pool.
// Grid: BATCH*SPLIT blocks over batch-aligned chunks; 256 threads.
// Phase A: thread-per-node gathers u rows of its incoming edges into registers.
// Phase B: 64-feature x 4-stride transform + smem-reduced pooling.
__global__ void __launch_bounds__(256, 4)
fused_kernel(const float* __restrict__ Wc, const float* __restrict__ bc) {
    int b     = blockIdx.x / SPLIT;
    int split = blockIdx.x % SPLIT;
    int start = g_bnd[b];
    int end   = g_bnd[b + 1];
    int total = end - start;
    int chunk = (total + SPLIT - 1) / SPLIT;
    int s0    = start + split * chunk;
    int s1    = min(s0 + chunk, end);

    __shared__ float sW[N_FEAT * HIDDEN];
    __shared__ float sb[HIDDEN];
    __shared__ __align__(16) float sx[TILE][FPAD];
    __shared__ float red[4][HIDDEN];

    for (int i = threadIdx.x; i < N_FEAT * HIDDEN; i += blockDim.x) sW[i] = Wc[i];
    if (threadIdx.x < HIDDEN) sb[threadIdx.x] = bc[threadIdx.x];
    __syncthreads();

    int j = threadIdx.x & 63;
    int s = threadIdx.x >> 6;

    float w0 = sW[0*HIDDEN+j], w1 = sW[1*HIDDEN+j], w2 = sW[2*HIDDEN+j], w3 = sW[3*HIDDEN+j];
    float w4 = sW[4*HIDDEN+j], w5 = sW[5*HIDDEN+j], w6 = sW[6*HIDDEN+j], w7 = sW[7*HIDDEN+j];
    float w8 = sW[8*HIDDEN+j], w9 = sW[9*HIDDEN+j], w10 = sW[10*HIDDEN+j];
    float bj  = sb[j];
    float acc = 0.0f;

    for (int t0 = s0; t0 < s1; t0 += TILE) {
        int cnt = min(TILE, s1 - t0);
        __syncthreads();
        // Phase A: gather + aggregate, one node per thread
        if (threadIdx.x < cnt) {
            int node = t0 + threadIdx.x;
            int beg = g_rowptr[node];
            int fin = g_rowptr[node + 1];
            float4 a0 = make_float4(0.f, 0.f, 0.f, 0.f);
            float4 a1 = a0, a2 = a0;
            for (int e = beg; e < fin; e++) {
                int src = g_srcs[e];
                if ((unsigned)src < N_NODES) {
                    const float4* ur = (const float4*)&g_xpad[src * FPAD];
                    float4 v0 = ur[0], v1 = ur[1], v2 = ur[2];
                    a0.x += v0.x; a0.y += v0.y; a0.z += v0.z; a0.w += v0.w;
                    a1.x += v1.x; a1.y += v1.y; a1.z += v1.z; a1.w += v1.w;
                    a2.x += v2.x; a2.y += v2.y; a2.z += v2.z;
                }
            }
            float dv = g_dinv[node];
            a0.x *= dv; a0.y *= dv; a0.z *= dv; a0.w *= dv;
            a1.x *= dv; a1.y *= dv; a1.z *= dv; a1.w *= dv;
            a2.x *= dv; a2.y *= dv; a2.z *= dv; a2.w = 0.0f;
            float4* row = (float4*)&sx[threadIdx.x][0];
            row[0] = a0; row[1] = a1; row[2] = a2;
        }
        __syncthreads();
        // Phase B: transform + ReLU + accumulate
        for (int n = s; n < cnt; n += 4) {
            float4 a = *(const float4*)&sx[n][0];
            float4 d4 = *(const float4*)&sx[n][4];
            float4 c4 = *(const float4*)&sx[n][8];
            float dot = bj;
            dot = fmaf(a.x,  w0,  dot);
            dot = fmaf(a.y,  w1,  dot);
            dot = fmaf(a.z,  w2,  dot);
            dot = fmaf(a.w,  w3,  dot);
            dot = fmaf(d4.x, w4,  dot);
            dot = fmaf(d4.y, w5,  dot);
            dot = fmaf(d4.z, w6,  dot);
            dot = fmaf(d4.w, w7,  dot);
            dot = fmaf(c4.x, w8,  dot);
            dot = fmaf(c4.y, w9,  dot);
            dot = fmaf(c4.z, w10, dot);
            acc += fmaxf(dot, 0.0f);
        }
    }

    red[s][j] = acc;
    __syncthreads();
    if (s == 0) {
        float tot = red[0][j] + red[1][j] + red[2][j] + red[3][j];
        atomicAdd(&g_pooled[b * HIDDEN + j], tot);
    }
}

// out[b][c] = (pooled[b]/max(cnt,1)) @ W_lin + b_lin
__global__ void final_kernel(const float* __restrict__ Wlin,
                             const float* __restrict__ blin,
                             float* __restrict__ out) {
    int t = blockIdx.x * blockDim.x + threadIdx.x;
    if (t < BATCH * N_CLASSES) {
        int b = t / N_CLASSES, c = t % N_CLASSES;
        int cnt   = g_bnd[b + 1] - g_bnd[b];
        float inv = 1.0f / fmaxf((float)cnt, 1.0f);
        float acc = blin[c];
        #pragma unroll 8
        for (int jj = 0; jj < HIDDEN; jj++)
            acc = fmaf(g_pooled[b * HIDDEN + jj] * inv, Wlin[jj * N_CLASSES + c], acc);
        out[t] = acc;
    }
}

extern "C" void kernel_launch(void* const* d_in, const int* in_sizes, int n_in,
                              void* d_out, int out_size) {
    const float* x     = (const float*)d_in[0];
    const int*   ei    = (const int*)d_in[1];     // int64 narrowed to int32 by harness
    const int*   batch = (const int*)d_in[3];
    const float* Wc    = (const float*)d_in[4];
    const float* bc    = (const float*)d_in[5];
    const float* Wlin  = (const float*)d_in[6];
    const float* blin  = (const float*)d_in[7];
    float*       out   = (float*)d_out;

    static void* p_count  = nullptr;
    static void* p_pooled = nullptr;
    if (!p_count) {
        cudaGetSymbolAddress(&p_count,  g_count);
        cudaGetSymbolAddress(&p_pooled, g_pooled);
    }

    cudaMemsetAsync(p_count,  0, sizeof(int)   * N_NODES);
    cudaMemsetAsync(p_pooled, 0, sizeof(float) * BATCH * HIDDEN);

    hist_kernel<<<(N_EDGES / 4 + 255) / 256, 256>>>(ei);
    scan1_kernel<<<NB_SCAN, SCAN_B>>>();
    scan2_kernel<<<1, SCAN_B>>>();
    scan3_kernel<<<(N_NODES + 255) / 256, 256>>>();
    dinv_kernel<<<(N_NODES + 255) / 256, 256>>>();
    pad_kernel<<<2048, 256>>>(x);
    bnd_kernel<<<(N_NODES / 4 + 255) / 256, 256>>>(batch);
    fill_kernel<<<(N_EDGES / 4 + 255) / 256, 256>>>(ei);
    fused_kernel<<<BATCH * SPLIT, 256>>>(Wc, bc);
    final_kernel<<<(BATCH * N_CLASSES + 127) / 128, 128>>>(Wlin, blin, out);
}

// round 7
// speedup vs baseline: 1.1613x; 1.0984x over previous
#include <cuda_runtime.h>

#define N_NODES   1000000
#define N_EDGES   2000000
#define N_FEAT    11
#define FPAD      12
#define HIDDEN    64
#define N_CLASSES 19
#define BATCH     128

#define SPLIT 16
#define TILE  256
#define NB_SCAN 977            // ceil(1M / 1024)

// ---- scratch (device globals; no allocs) ----
__device__ __align__(16) int   g_count[N_NODES];
__device__ __align__(16) int   g_rowptr[N_NODES + 4];
__device__ __align__(16) int   g_cursor[N_NODES];
__device__ __align__(16) int   g_srcs[N_EDGES];
__device__ __align__(16) float g_dinv[N_NODES];
__device__ __align__(16) float g_xpad[N_NODES * FPAD];  // u = x * dinv[row]
__device__ float g_pooled[BATCH * HIDDEN];
__device__ int   g_bnd[BATCH + 1];
__device__ int   g_bsum[1024];
__device__ int   g_boffs[1024];

typedef unsigned long long ull;
__device__ __forceinline__ ull fma2(ull a, ull b, ull c) {
    ull d; asm("fma.rn.f32x2 %0, %1, %2, %3;" : "=l"(d) : "l"(a), "l"(b), "l"(c)); return d;
}
__device__ __forceinline__ ull pack2(float lo, float hi) {
    ull d; asm("mov.b64 %0, {%1, %2};" : "=l"(d) : "f"(lo), "f"(hi)); return d;
}
__device__ __forceinline__ void unpack2(float& lo, float& hi, ull v) {
    asm("mov.b64 {%0, %1}, %2;" : "=f"(lo), "=f"(hi) : "l"(v));
}

// ---- fused histogram (in-degree) + batch segment boundaries ----
__global__ void hist_bnd_kernel(const int* __restrict__ ei,
                                const int* __restrict__ batch) {
    int q = blockIdx.x * blockDim.x + threadIdx.x;
    if (q < N_EDGES / 4) {
        int4 cc = ((const int4*)(ei + N_EDGES))[q];
        if ((unsigned)cc.x < N_NODES) atomicAdd(&g_count[cc.x], 1);
        if ((unsigned)cc.y < N_NODES) atomicAdd(&g_count[cc.y], 1);
        if ((unsigned)cc.z < N_NODES) atomicAdd(&g_count[cc.z], 1);
        if ((unsigned)cc.w < N_NODES) atomicAdd(&g_count[cc.w], 1);
    }
    if (q < N_NODES / 4) {
        int i0 = q * 4;
        int4 v = ((const int4*)batch)[q];
        int prev = (i0 == 0) ? -1 : batch[i0 - 1];
        int vals[4] = {v.x, v.y, v.z, v.w};
        #pragma unroll
        for (int t = 0; t < 4; t++) {
            int cur = vals[t];
            for (int k = prev + 1; k <= cur && k <= BATCH; k++) g_bnd[k] = i0 + t;
            prev = cur;
        }
        if (i0 + 4 == N_NODES) {
            for (int k = prev + 1; k <= BATCH; k++) g_bnd[k] = N_NODES;
        }
    }
}

// ---- shfl-based block scan: 256 threads x 4 elems = 1024/block ----
__global__ void scan1_kernel() {
    int tid = threadIdx.x, lane = tid & 31, wid = tid >> 5;
    int idx4 = blockIdx.x * 256 + tid;
    int4 v = (idx4 * 4 < N_NODES) ? ((const int4*)g_count)[idx4] : make_int4(0,0,0,0);
    int s = v.x + v.y + v.z + v.w;
    int incl = s;
    #pragma unroll
    for (int o = 1; o < 32; o <<= 1) {
        int t = __shfl_up_sync(0xffffffffu, incl, o);
        if (lane >= o) incl += t;
    }
    __shared__ int wsum[8];
    if (lane == 31) wsum[wid] = incl;
    __syncthreads();
    int woff = 0;
    #pragma unroll
    for (int w = 0; w < 8; w++) if (w < wid) woff += wsum[w];
    int excl = woff + incl - s;
    if (idx4 * 4 < N_NODES) {
        int4 r;
        r.x = excl; r.y = excl + v.x; r.z = r.y + v.y; r.w = r.z + v.z;
        ((int4*)g_rowptr)[idx4] = r;
    }
    if (tid == 255) g_bsum[blockIdx.x] = woff + incl;
}

__global__ void scan2_kernel() {
    int tid = threadIdx.x, lane = tid & 31, wid = tid >> 5;
    int i0 = tid * 4;
    int v[4];
    #pragma unroll
    for (int k = 0; k < 4; k++) v[k] = (i0 + k < NB_SCAN) ? g_bsum[i0 + k] : 0;
    int s = v[0] + v[1] + v[2] + v[3];
    int incl = s;
    #pragma unroll
    for (int o = 1; o < 32; o <<= 1) {
        int t = __shfl_up_sync(0xffffffffu, incl, o);
        if (lane >= o) incl += t;
    }
    __shared__ int wsum[8];
    if (lane == 31) wsum[wid] = incl;
    __syncthreads();
    int woff = 0;
    #pragma unroll
    for (int w = 0; w < 8; w++) if (w < wid) woff += wsum[w];
    int excl = woff + incl - s;
    #pragma unroll
    for (int k = 0; k < 4; k++) {
        if (i0 + k < NB_SCAN) g_boffs[i0 + k] = excl;
        excl += v[k];
    }
    if (tid == 255) g_rowptr[N_NODES] = woff + incl;   // total
}

// ---- fused: add block offsets + cursor + dinv + pad (u = x * dinv) ----
__global__ void finish_kernel(const float* __restrict__ x) {
    int q = blockIdx.x * blockDim.x + threadIdx.x;
    if (q >= N_NODES / 4) return;
    int off = g_boffs[q >> 8];
    int4 rp = ((const int4*)g_rowptr)[q];
    rp.x += off; rp.y += off; rp.z += off; rp.w += off;
    ((int4*)g_rowptr)[q] = rp;
    ((int4*)g_cursor)[q] = rp;
    int4 c4 = ((const int4*)g_count)[q];
    float4 dv;
    dv.x = (c4.x > 0) ? rsqrtf((float)c4.x) : 0.0f;
    dv.y = (c4.y > 0) ? rsqrtf((float)c4.y) : 0.0f;
    dv.z = (c4.z > 0) ? rsqrtf((float)c4.z) : 0.0f;
    dv.w = (c4.w > 0) ? rsqrtf((float)c4.w) : 0.0f;
    ((float4*)g_dinv)[q] = dv;
    // pad: 4 nodes x 11 feats = 44 floats (16B-aligned slab)
    float a[44];
    const float4* xs = (const float4*)(x + (long long)q * 44);
    #pragma unroll
    for (int m = 0; m < 11; m++) {
        float4 t = xs[m];
        a[m*4+0] = t.x; a[m*4+1] = t.y; a[m*4+2] = t.z; a[m*4+3] = t.w;
    }
    float dvs[4] = {dv.x, dv.y, dv.z, dv.w};
    #pragma unroll
    for (int k = 0; k < 4; k++) {
        float d = dvs[k];
        float4* dst = (float4*)&g_xpad[(q * 4 + k) * FPAD];
        dst[0] = make_float4(a[k*11+0]*d, a[k*11+1]*d, a[k*11+2]*d,  a[k*11+3]*d);
        dst[1] = make_float4(a[k*11+4]*d, a[k*11+5]*d, a[k*11+6]*d,  a[k*11+7]*d);
        dst[2] = make_float4(a[k*11+8]*d, a[k*11+9]*d, a[k*11+10]*d, 0.0f);
    }
}

// ---- CSR fill ----
__global__ void fill_kernel(const int* __restrict__ ei) {
    int q = blockIdx.x * blockDim.x + threadIdx.x;
    if (q >= N_EDGES / 4) return;
    int4 rr = ((const int4*)ei)[q];
    int4 cc = ((const int4*)(ei + N_EDGES))[q];
    #pragma unroll
    for (int k = 0; k < 4; k++) {
        int r = (k == 0) ? rr.x : (k == 1) ? rr.y : (k == 2) ? rr.z : rr.w;
        int c = (k == 0) ? cc.x : (k == 1) ? cc.y : (k == 2) ? cc.z : cc.w;
        if ((unsigned)c < N_NODES) {
            int pos = atomicAdd(&g_cursor[c], 1);
            if ((unsigned)pos < N_EDGES) g_srcs[pos] = r;
        }
    }
}

// ---- fused CSR-gather + transform(f32x2) + ReLU + pool ----
__global__ void __launch_bounds__(256)
fused_kernel(const float* __restrict__ Wc, const float* __restrict__ bc) {
    int b     = blockIdx.x >> 4;      // SPLIT=16
    int split = blockIdx.x & 15;
    int start = g_bnd[b];
    int end   = g_bnd[b + 1];
    int total = end - start;
    int chunk = (total + SPLIT - 1) / SPLIT;
    int s0    = start + split * chunk;
    int s1    = min(s0 + chunk, end);

    __shared__ float sW[N_FEAT * HIDDEN];
    __shared__ float sb[HIDDEN];
    __shared__ __align__(16) float sxT[N_FEAT][TILE];   // feature-major tile
    __shared__ float red[4][HIDDEN];

    for (int i = threadIdx.x; i < N_FEAT * HIDDEN; i += blockDim.x) sW[i] = Wc[i];
    if (threadIdx.x < HIDDEN) sb[threadIdx.x] = bc[threadIdx.x];
    __syncthreads();

    int j = threadIdx.x & 63;
    int s = threadIdx.x >> 6;

    ull w2[N_FEAT];
    #pragma unroll
    for (int f = 0; f < N_FEAT; f++) { float w = sW[f * HIDDEN + j]; w2[f] = pack2(w, w); }
    float bj  = sb[j];
    ull   bj2 = pack2(bj, bj);
    float acc = 0.0f;
    int   padsum = 0;

    for (int t0 = s0; t0 < s1; t0 += TILE) {
        int cnt  = min(TILE, s1 - t0);
        int cntp = (cnt + 3) & ~3;
        __syncthreads();
        // Phase A: gather + aggregate, one node per thread (feature-major store)
        if (threadIdx.x < cntp) {
            float a[FPAD];
            #pragma unroll
            for (int f = 0; f < FPAD; f++) a[f] = 0.0f;
            if (threadIdx.x < cnt) {
                int node = t0 + threadIdx.x;
                int beg = g_rowptr[node];
                int fin = g_rowptr[node + 1];
                for (int e = beg; e < fin; e++) {
                    int src = g_srcs[e];
                    if ((unsigned)src < N_NODES) {
                        const float4* ur = (const float4*)&g_xpad[src * FPAD];
                        float4 v0 = ur[0], v1 = ur[1], v2 = ur[2];
                        a[0] += v0.x; a[1] += v0.y; a[2]  += v0.z; a[3] += v0.w;
                        a[4] += v1.x; a[5] += v1.y; a[6]  += v1.z; a[7] += v1.w;
                        a[8] += v2.x; a[9] += v2.y; a[10] += v2.z;
                    }
                }
                float dv = g_dinv[node];
                #pragma unroll
                for (int f = 0; f < N_FEAT; f++) a[f] *= dv;
            }
            #pragma unroll
            for (int f = 0; f < N_FEAT; f++) sxT[f][threadIdx.x] = a[f];
        }
        __syncthreads();
        // Phase B: packed f32x2 transform, 4 nodes per iteration
        for (int n0 = s * 4; n0 < cntp; n0 += 16) {
            ull d0 = bj2, d1 = bj2;
            #pragma unroll
            for (int f = 0; f < N_FEAT; f++) {
                ulonglong2 v = *(const ulonglong2*)&sxT[f][n0];
                d0 = fma2(v.x, w2[f], d0);
                d1 = fma2(v.y, w2[f], d1);
            }
            float h0, h1, h2, h3;
            unpack2(h0, h1, d0);
            unpack2(h2, h3, d1);
            acc += fmaxf(h0, 0.0f) + fmaxf(h1, 0.0f) + fmaxf(h2, 0.0f) + fmaxf(h3, 0.0f);
        }
        // padded columns contributed relu(bj) each; subtract analytically
        int padc = cntp - cnt;
        if (padc && (((cnt >> 2) & 3) == s)) padsum += padc;
    }

    acc -= (float)padsum * fmaxf(bj, 0.0f);

    red[s][j] = acc;
    __syncthreads();
    if (s == 0) {
        float tot = red[0][j] + red[1][j] + red[2][j] + red[3][j];
        atomicAdd(&g_pooled[b * HIDDEN + j], tot);
    }
}

// ---- out[b][c] = (pooled[b]/max(cnt,1)) @ W_lin + b_lin ----
__global__ void final_kernel(const float* __restrict__ Wlin,
                             const float* __restrict__ blin,
                             float* __restrict__ out) {
    int t = blockIdx.x * blockDim.x + threadIdx.x;
    if (t < BATCH * N_CLASSES) {
        int b = t / N_CLASSES, c = t % N_CLASSES;
        int cnt   = g_bnd[b + 1] - g_bnd[b];
        float inv = 1.0f / fmaxf((float)cnt, 1.0f);
        float acc = blin[c];
        #pragma unroll 8
        for (int jj = 0; jj < HIDDEN; jj++)
            acc = fmaf(g_pooled[b * HIDDEN + jj] * inv, Wlin[jj * N_CLASSES + c], acc);
        out[t] = acc;
    }
}

extern "C" void kernel_launch(void* const* d_in, const int* in_sizes, int n_in,
                              void* d_out, int out_size) {
    const float* x     = (const float*)d_in[0];
    const int*   ei    = (const int*)d_in[1];     // int64 narrowed to int32 by harness
    const int*   batch = (const int*)d_in[3];
    const float* Wc    = (const float*)d_in[4];
    const float* bc    = (const float*)d_in[5];
    const float* Wlin  = (const float*)d_in[6];
    const float* blin  = (const float*)d_in[7];
    float*       out   = (float*)d_out;

    static void* p_count  = nullptr;
    static void* p_pooled = nullptr;
    if (!p_count) {
        cudaGetSymbolAddress(&p_count,  g_count);
        cudaGetSymbolAddress(&p_pooled, g_pooled);
    }

    cudaMemsetAsync(p_count,  0, sizeof(int)   * N_NODES);
    cudaMemsetAsync(p_pooled, 0, sizeof(float) * BATCH * HIDDEN);

    hist_bnd_kernel<<<(N_EDGES / 4 + 255) / 256, 256>>>(ei, batch);
    scan1_kernel<<<NB_SCAN, 256>>>();
    scan2_kernel<<<1, 256>>>();
    finish_kernel<<<(N_NODES / 4 + 255) / 256, 256>>>(x);
    fill_kernel<<<(N_EDGES / 4 + 255) / 256, 256>>>(ei);
    fused_kernel<<<BATCH * SPLIT, 256>>>(Wc, bc);
    final_kernel<<<(BATCH * N_CLASSES + 127) / 128, 128>>>(Wlin, blin, out);
}

// round 11
// speedup vs baseline: 1.2104x; 1.0422x over previous
#include <cuda_runtime.h>

#define N_NODES   1000000
#define N_EDGES   2000000
#define N_FEAT    11
#define FPAD      12
#define HIDDEN    64
#define N_CLASSES 19
#define BATCH     128

#define SPLIT 16
#define TILE  256
#define NB_SCAN 977            // ceil(1M / 1024)
#define FIN_NODES 256

// ---- scratch (device globals; no allocs) ----
__device__ __align__(16) int   g_count[N_NODES];
__device__ __align__(16) int   g_rowptr[N_NODES + 4];   // after fill: rowptr[i] = end of node i
__device__ __align__(16) int   g_srcs[N_EDGES];
__device__ __align__(16) float g_dinv[N_NODES];
__device__ __align__(16) float g_xpad[N_NODES * FPAD];  // u = x * dinv[row]
__device__ float g_pooled[BATCH * HIDDEN];
__device__ int   g_bnd[BATCH + 1];
__device__ int   g_bsum[1024];
__device__ int   g_boffs[1024];

typedef unsigned long long ull;
__device__ __forceinline__ ull fma2(ull a, ull b, ull c) {
    ull d; asm("fma.rn.f32x2 %0, %1, %2, %3;" : "=l"(d) : "l"(a), "l"(b), "l"(c)); return d;
}
__device__ __forceinline__ ull pack2(float lo, float hi) {
    ull d; asm("mov.b64 %0, {%1, %2};" : "=l"(d) : "f"(lo), "f"(hi)); return d;
}
__device__ __forceinline__ void unpack2(float& lo, float& hi, ull v) {
    asm("mov.b64 {%0, %1}, %2;" : "=f"(lo), "=f"(hi) : "l"(v));
}

// ---- fused histogram (in-degree) + batch segment boundaries ----
__global__ void hist_bnd_kernel(const int* __restrict__ ei,
                                const int* __restrict__ batch) {
    int q = blockIdx.x * blockDim.x + threadIdx.x;
    if (q < N_EDGES / 4) {
        int4 cc = ((const int4*)(ei + N_EDGES))[q];
        if ((unsigned)cc.x < N_NODES) atomicAdd(&g_count[cc.x], 1);
        if ((unsigned)cc.y < N_NODES) atomicAdd(&g_count[cc.y], 1);
        if ((unsigned)cc.z < N_NODES) atomicAdd(&g_count[cc.z], 1);
        if ((unsigned)cc.w < N_NODES) atomicAdd(&g_count[cc.w], 1);
    }
    if (q < N_NODES / 4) {
        int i0 = q * 4;
        int4 v = ((const int4*)batch)[q];
        int prev = (i0 == 0) ? -1 : batch[i0 - 1];
        int vals[4] = {v.x, v.y, v.z, v.w};
        #pragma unroll
        for (int t = 0; t < 4; t++) {
            int cur = vals[t];
            for (int k = prev + 1; k <= cur && k <= BATCH; k++) g_bnd[k] = i0 + t;
            prev = cur;
        }
        if (i0 + 4 == N_NODES) {
            for (int k = prev + 1; k <= BATCH; k++) g_bnd[k] = N_NODES;
        }
    }
}

// ---- shfl-based block scan: 256 threads x 4 elems = 1024/block ----
__global__ void scan1_kernel() {
    int tid = threadIdx.x, lane = tid & 31, wid = tid >> 5;
    int idx4 = blockIdx.x * 256 + tid;
    int4 v = (idx4 * 4 < N_NODES) ? ((const int4*)g_count)[idx4] : make_int4(0,0,0,0);
    int s = v.x + v.y + v.z + v.w;
    int incl = s;
    #pragma unroll
    for (int o = 1; o < 32; o <<= 1) {
        int t = __shfl_up_sync(0xffffffffu, incl, o);
        if (lane >= o) incl += t;
    }
    __shared__ int wsum[8];
    if (lane == 31) wsum[wid] = incl;
    __syncthreads();
    int woff = 0;
    #pragma unroll
    for (int w = 0; w < 8; w++) if (w < wid) woff += wsum[w];
    int excl = woff + incl - s;
    if (idx4 * 4 < N_NODES) {
        int4 r;
        r.x = excl; r.y = excl + v.x; r.z = r.y + v.y; r.w = r.z + v.z;
        ((int4*)g_rowptr)[idx4] = r;
    }
    if (tid == 255) g_bsum[blockIdx.x] = woff + incl;
}

__global__ void scan2_kernel() {
    int tid = threadIdx.x, lane = tid & 31, wid = tid >> 5;
    int i0 = tid * 4;
    int v[4];
    #pragma unroll
    for (int k = 0; k < 4; k++) v[k] = (i0 + k < NB_SCAN) ? g_bsum[i0 + k] : 0;
    int s = v[0] + v[1] + v[2] + v[3];
    int incl = s;
    #pragma unroll
    for (int o = 1; o < 32; o <<= 1) {
        int t = __shfl_up_sync(0xffffffffu, incl, o);
        if (lane >= o) incl += t;
    }
    __shared__ int wsum[8];
    if (lane == 31) wsum[wid] = incl;
    __syncthreads();
    int woff = 0;
    #pragma unroll
    for (int w = 0; w < 8; w++) if (w < wid) woff += wsum[w];
    int excl = woff + incl - s;
    #pragma unroll
    for (int k = 0; k < 4; k++) {
        if (i0 + k < NB_SCAN) g_boffs[i0 + k] = excl;
        excl += v[k];
    }
}

// ---- coalesced finish: rowptr offsets + dinv + pad (u = x * dinv) ----
// Block handles 256 nodes. Coalesced float4 in (x slab -> smem), coalesced
// float4 out (xpad), int4/float4 for count/rowptr/dinv.
__global__ void __launch_bounds__(256)
finish_kernel(const float* __restrict__ x) {
    __shared__ float sx[FIN_NODES * N_FEAT];   // 11 KB
    __shared__ float sdv[FIN_NODES];
    int base = blockIdx.x * FIN_NODES;
    int cnt  = min(FIN_NODES, N_NODES - base);
    int tid  = threadIdx.x;

    // 1) coalesced x slab load (cnt*11 floats; divisible by 4 per block layout)
    {
        const float4* xs = (const float4*)(x + (long long)base * N_FEAT);
        float4* s4 = (float4*)sx;
        int nv = cnt * N_FEAT / 4;
        for (int i = tid; i < nv; i += FIN_NODES) s4[i] = xs[i];
    }
    // 2) count -> dinv, rowptr += block offset
    if (tid < cnt / 4) {
        int q   = base / 4 + tid;
        int off = g_boffs[base >> 10];
        int4 rp = ((const int4*)g_rowptr)[q];
        rp.x += off; rp.y += off; rp.z += off; rp.w += off;
        ((int4*)g_rowptr)[q] = rp;
        int4 c4 = ((const int4*)g_count)[q];
        float4 dv;
        dv.x = (c4.x > 0) ? rsqrtf((float)c4.x) : 0.0f;
        dv.y = (c4.y > 0) ? rsqrtf((float)c4.y) : 0.0f;
        dv.z = (c4.z > 0) ? rsqrtf((float)c4.z) : 0.0f;
        dv.w = (c4.w > 0) ? rsqrtf((float)c4.w) : 0.0f;
        ((float4*)g_dinv)[q] = dv;
        *(float4*)&sdv[tid * 4] = dv;
    }
    __syncthreads();
    // 3) coalesced xpad write: 3 float4 per node, linear
    {
        float4* dst = (float4*)&g_xpad[(long long)base * FPAD];
        int nv = cnt * 3;
        for (int i = tid; i < nv; i += FIN_NODES) {
            int node = i / 3, comp = i - node * 3;
            float dv = sdv[node];
            const float* a = &sx[node * N_FEAT];
            float4 v;
            if (comp == 0)      v = make_float4(a[0]*dv, a[1]*dv, a[2]*dv,  a[3]*dv);
            else if (comp == 1) v = make_float4(a[4]*dv, a[5]*dv, a[6]*dv,  a[7]*dv);
            else                v = make_float4(a[8]*dv, a[9]*dv, a[10]*dv, 0.0f);
            dst[i] = v;
        }
    }
}

// ---- CSR fill: bump rowptr in place; after this rowptr[i] = end(node i) ----
__global__ void fill_kernel(const int* __restrict__ ei) {
    int q = blockIdx.x * blockDim.x + threadIdx.x;
    if (q >= N_EDGES / 4) return;
    int4 rr = ((const int4*)ei)[q];
    int4 cc = ((const int4*)(ei + N_EDGES))[q];
    #pragma unroll
    for (int k = 0; k < 4; k++) {
        int r = (k == 0) ? rr.x : (k == 1) ? rr.y : (k == 2) ? rr.z : rr.w;
        int c = (k == 0) ? cc.x : (k == 1) ? cc.y : (k == 2) ? cc.z : cc.w;
        if ((unsigned)c < N_NODES) {
            int pos = atomicAdd(&g_rowptr[c], 1);
            if ((unsigned)pos < N_EDGES) g_srcs[pos] = r;
        }
    }
}

// ---- fused CSR-gather + transform(f32x2) + ReLU + pool ----
// rowptr semantics post-fill: beg = node ? rowptr[node-1] : 0, fin = rowptr[node]
__global__ void __launch_bounds__(256)
fused_kernel(const float* __restrict__ Wc, const float* __restrict__ bc) {
    int b     = blockIdx.x >> 4;      // SPLIT=16
    int split = blockIdx.x & 15;
    int start = g_bnd[b];
    int end   = g_bnd[b + 1];
    int total = end - start;
    int chunk = (total + SPLIT - 1) / SPLIT;
    int s0    = start + split * chunk;
    int s1    = min(s0 + chunk, end);

    __shared__ float sW[N_FEAT * HIDDEN];
    __shared__ float sb[HIDDEN];
    __shared__ __align__(16) float sxT[N_FEAT][TILE];   // feature-major tile
    __shared__ float red[4][HIDDEN];

    for (int i = threadIdx.x; i < N_FEAT * HIDDEN; i += blockDim.x) sW[i] = Wc[i];
    if (threadIdx.x < HIDDEN) sb[threadIdx.x] = bc[threadIdx.x];
    __syncthreads();

    int j = threadIdx.x & 63;
    int s = threadIdx.x >> 6;

    ull w2[N_FEAT];
    #pragma unroll
    for (int f = 0; f < N_FEAT; f++) { float w = sW[f * HIDDEN + j]; w2[f] = pack2(w, w); }
    float bj  = sb[j];
    ull   bj2 = pack2(bj, bj);
    float acc = 0.0f;
    int   padsum = 0;

    for (int t0 = s0; t0 < s1; t0 += TILE) {
        int cnt  = min(TILE, s1 - t0);
        int cntp = (cnt + 3) & ~3;
        __syncthreads();
        // Phase A: gather + aggregate, one node per thread (feature-major store)
        if (threadIdx.x < cntp) {
            float a[FPAD];
            #pragma unroll
            for (int f = 0; f < FPAD; f++) a[f] = 0.0f;
            if (threadIdx.x < cnt) {
                int node = t0 + threadIdx.x;
                int beg = (node > 0) ? g_rowptr[node - 1] : 0;
                int fin = g_rowptr[node];
                for (int e = beg; e < fin; e++) {
                    int src = g_srcs[e];
                    if ((unsigned)src < N_NODES) {
                        const float4* ur = (const float4*)&g_xpad[src * FPAD];
                        float4 v0 = ur[0], v1 = ur[1], v2 = ur[2];
                        a[0] += v0.x; a[1] += v0.y; a[2]  += v0.z; a[3] += v0.w;
                        a[4] += v1.x; a[5] += v1.y; a[6]  += v1.z; a[7] += v1.w;
                        a[8] += v2.x; a[9] += v2.y; a[10] += v2.z;
                    }
                }
                float dv = g_dinv[node];
                #pragma unroll
                for (int f = 0; f < N_FEAT; f++) a[f] *= dv;
            }
            #pragma unroll
            for (int f = 0; f < N_FEAT; f++) sxT[f][threadIdx.x] = a[f];
        }
        __syncthreads();
        // Phase B: packed f32x2 transform, 4 nodes per iteration
        for (int n0 = s * 4; n0 < cntp; n0 += 16) {
            ull d0 = bj2, d1 = bj2;
            #pragma unroll
            for (int f = 0; f < N_FEAT; f++) {
                ulonglong2 v = *(const ulonglong2*)&sxT[f][n0];
                d0 = fma2(v.x, w2[f], d0);
                d1 = fma2(v.y, w2[f], d1);
            }
            float h0, h1, h2, h3;
            unpack2(h0, h1, d0);
            unpack2(h2, h3, d1);
            acc += fmaxf(h0, 0.0f) + fmaxf(h1, 0.0f) + fmaxf(h2, 0.0f) + fmaxf(h3, 0.0f);
        }
        // padded columns contributed relu(bj) each; subtract analytically
        int padc = cntp - cnt;
        if (padc && (((cnt >> 2) & 3) == s)) padsum += padc;
    }

    acc -= (float)padsum * fmaxf(bj, 0.0f);

    red[s][j] = acc;
    __syncthreads();
    if (s == 0) {
        float tot = red[0][j] + red[1][j] + red[2][j] + red[3][j];
        atomicAdd(&g_pooled[b * HIDDEN + j], tot);
    }
}

// ---- out[b][c] = (pooled[b]/max(cnt,1)) @ W_lin + b_lin ----
__global__ void final_kernel(const float* __restrict__ Wlin,
                             const float* __restrict__ blin,
                             float* __restrict__ out) {
    int t = blockIdx.x * blockDim.x + threadIdx.x;
    if (t < BATCH * N_CLASSES) {
        int b = t / N_CLASSES, c = t % N_CLASSES;
        int cnt   = g_bnd[b + 1] - g_bnd[b];
        float inv = 1.0f / fmaxf((float)cnt, 1.0f);
        float acc = blin[c];
        #pragma unroll 8
        for (int jj = 0; jj < HIDDEN; jj++)
            acc = fmaf(g_pooled[b * HIDDEN + jj] * inv, Wlin[jj * N_CLASSES + c], acc);
        out[t] = acc;
    }
}

extern "C" void kernel_launch(void* const* d_in, const int* in_sizes, int n_in,
                              void* d_out, int out_size) {
    const float* x     = (const float*)d_in[0];
    const int*   ei    = (const int*)d_in[1];     // int64 narrowed to int32 by harness
    const int*   batch = (const int*)d_in[3];
    const float* Wc    = (const float*)d_in[4];
    const float* bc    = (const float*)d_in[5];
    const float* Wlin  = (const float*)d_in[6];
    const float* blin  = (const float*)d_in[7];
    float*       out   = (float*)d_out;

    static void* p_count  = nullptr;
    static void* p_pooled = nullptr;
    if (!p_count) {
        cudaGetSymbolAddress(&p_count,  g_count);
        cudaGetSymbolAddress(&p_pooled, g_pooled);
    }

    cudaMemsetAsync(p_count,  0, sizeof(int)   * N_NODES);
    cudaMemsetAsync(p_pooled, 0, sizeof(float) * BATCH * HIDDEN);

    hist_bnd_kernel<<<(N_EDGES / 4 + 255) / 256, 256>>>(ei, batch);
    scan1_kernel<<<NB_SCAN, 256>>>();
    scan2_kernel<<<1, 256>>>();
    finish_kernel<<<(N_NODES + FIN_NODES - 1) / FIN_NODES, 256>>>(x);
    fill_kernel<<<(N_EDGES / 4 + 255) / 256, 256>>>(ei);
    fused_kernel<<<BATCH * SPLIT, 256>>>(Wc, bc);
    final_kernel<<<(BATCH * N_CLASSES + 127) / 128, 128>>>(Wlin, blin, out);
}

// round 12
// speedup vs baseline: 1.3319x; 1.1004x over previous
#include <cuda_runtime.h>
#include <cuda_fp16.h>

#define N_NODES   1000000
#define N_EDGES   2000000
#define N_FEAT    11
#define HPAD      16           // fp16 halves per padded u row (32 bytes)
#define HIDDEN    64
#define N_CLASSES 19
#define BATCH     128

#define SPLIT 16
#define TILE  256
#define NB_SCAN 977            // ceil(1M / 1024)
#define FIN_NODES 256

// ---- scratch (device globals; no allocs) ----
__device__ __align__(16) int    g_count[N_NODES];
__device__ __align__(16) int    g_rowptr[N_NODES + 4];   // after fill: rowptr[i] = end of node i
__device__ __align__(16) int    g_srcs[N_EDGES];
__device__ __align__(16) float  g_dinv[N_NODES];
__device__ __align__(16) __half g_xpad[N_NODES * HPAD];  // u = x * dinv[row], fp16, 32B rows
__device__ float g_pooled[BATCH * HIDDEN];
__device__ int   g_bnd[BATCH + 1];
__device__ int   g_bsum[1024];
__device__ int   g_boffs[1024];

typedef unsigned long long ull;
__device__ __forceinline__ ull fma2(ull a, ull b, ull c) {
    ull d; asm("fma.rn.f32x2 %0, %1, %2, %3;" : "=l"(d) : "l"(a), "l"(b), "l"(c)); return d;
}
__device__ __forceinline__ ull pack2(float lo, float hi) {
    ull d; asm("mov.b64 %0, {%1, %2};" : "=l"(d) : "f"(lo), "f"(hi)); return d;
}
__device__ __forceinline__ void unpack2(float& lo, float& hi, ull v) {
    asm("mov.b64 {%0, %1}, %2;" : "=f"(lo), "=f"(hi) : "l"(v));
}

// ---- fused histogram (in-degree) + batch segment boundaries ----
__global__ void hist_bnd_kernel(const int* __restrict__ ei,
                                const int* __restrict__ batch) {
    int q = blockIdx.x * blockDim.x + threadIdx.x;
    if (q < N_EDGES / 4) {
        int4 cc = ((const int4*)(ei + N_EDGES))[q];
        if ((unsigned)cc.x < N_NODES) atomicAdd(&g_count[cc.x], 1);
        if ((unsigned)cc.y < N_NODES) atomicAdd(&g_count[cc.y], 1);
        if ((unsigned)cc.z < N_NODES) atomicAdd(&g_count[cc.z], 1);
        if ((unsigned)cc.w < N_NODES) atomicAdd(&g_count[cc.w], 1);
    }
    if (q < N_NODES / 4) {
        int i0 = q * 4;
        int4 v = ((const int4*)batch)[q];
        int prev = (i0 == 0) ? -1 : batch[i0 - 1];
        int vals[4] = {v.x, v.y, v.z, v.w};
        #pragma unroll
        for (int t = 0; t < 4; t++) {
            int cur = vals[t];
            for (int k = prev + 1; k <= cur && k <= BATCH; k++) g_bnd[k] = i0 + t;
            prev = cur;
        }
        if (i0 + 4 == N_NODES) {
            for (int k = prev + 1; k <= BATCH; k++) g_bnd[k] = N_NODES;
        }
    }
}

// ---- shfl-based block scan: 256 threads x 4 elems = 1024/block ----
__global__ void scan1_kernel() {
    int tid = threadIdx.x, lane = tid & 31, wid = tid >> 5;
    int idx4 = blockIdx.x * 256 + tid;
    int4 v = (idx4 * 4 < N_NODES) ? ((const int4*)g_count)[idx4] : make_int4(0,0,0,0);
    int s = v.x + v.y + v.z + v.w;
    int incl = s;
    #pragma unroll
    for (int o = 1; o < 32; o <<= 1) {
        int t = __shfl_up_sync(0xffffffffu, incl, o);
        if (lane >= o) incl += t;
    }
    __shared__ int wsum[8];
    if (lane == 31) wsum[wid] = incl;
    __syncthreads();
    int woff = 0;
    #pragma unroll
    for (int w = 0; w < 8; w++) if (w < wid) woff += wsum[w];
    int excl = woff + incl - s;
    if (idx4 * 4 < N_NODES) {
        int4 r;
        r.x = excl; r.y = excl + v.x; r.z = r.y + v.y; r.w = r.z + v.z;
        ((int4*)g_rowptr)[idx4] = r;
    }
    if (tid == 255) g_bsum[blockIdx.x] = woff + incl;
}

__global__ void scan2_kernel() {
    int tid = threadIdx.x, lane = tid & 31, wid = tid >> 5;
    int i0 = tid * 4;
    int v[4];
    #pragma unroll
    for (int k = 0; k < 4; k++) v[k] = (i0 + k < NB_SCAN) ? g_bsum[i0 + k] : 0;
    int s = v[0] + v[1] + v[2] + v[3];
    int incl = s;
    #pragma unroll
    for (int o = 1; o < 32; o <<= 1) {
        int t = __shfl_up_sync(0xffffffffu, incl, o);
        if (lane >= o) incl += t;
    }
    __shared__ int wsum[8];
    if (lane == 31) wsum[wid] = incl;
    __syncthreads();
    int woff = 0;
    #pragma unroll
    for (int w = 0; w < 8; w++) if (w < wid) woff += wsum[w];
    int excl = woff + incl - s;
    #pragma unroll
    for (int k = 0; k < 4; k++) {
        if (i0 + k < NB_SCAN) g_boffs[i0 + k] = excl;
        excl += v[k];
    }
}

// ---- coalesced finish: rowptr offsets + dinv + fp16 pad (u = x * dinv) ----
__global__ void __launch_bounds__(256)
finish_kernel(const float* __restrict__ x) {
    __shared__ float sx[FIN_NODES * N_FEAT];   // 11 KB
    __shared__ float sdv[FIN_NODES];
    int base = blockIdx.x * FIN_NODES;
    int cnt  = min(FIN_NODES, N_NODES - base);
    int tid  = threadIdx.x;

    // 1) coalesced x slab load
    {
        const float4* xs = (const float4*)(x + (long long)base * N_FEAT);
        float4* s4 = (float4*)sx;
        int nv = cnt * N_FEAT / 4;
        for (int i = tid; i < nv; i += FIN_NODES) s4[i] = xs[i];
    }
    // 2) count -> dinv, rowptr += block offset
    if (tid < cnt / 4) {
        int q   = base / 4 + tid;
        int off = g_boffs[base >> 10];
        int4 rp = ((const int4*)g_rowptr)[q];
        rp.x += off; rp.y += off; rp.z += off; rp.w += off;
        ((int4*)g_rowptr)[q] = rp;
        int4 c4 = ((const int4*)g_count)[q];
        float4 dv;
        dv.x = (c4.x > 0) ? rsqrtf((float)c4.x) : 0.0f;
        dv.y = (c4.y > 0) ? rsqrtf((float)c4.y) : 0.0f;
        dv.z = (c4.z > 0) ? rsqrtf((float)c4.z) : 0.0f;
        dv.w = (c4.w > 0) ? rsqrtf((float)c4.w) : 0.0f;
        ((float4*)g_dinv)[q] = dv;
        *(float4*)&sdv[tid * 4] = dv;
    }
    __syncthreads();
    // 3) coalesced fp16 xpad write: 2 uint4 (8 half2) per node
    {
        uint4* dst = (uint4*)&g_xpad[(long long)base * HPAD];
        int nv = cnt * 2;
        for (int i = tid; i < nv; i += FIN_NODES) {
            int node = i >> 1, hi = i & 1;
            float dv = sdv[node];
            const float* a = &sx[node * N_FEAT];
            __half2 h[4];
            if (hi == 0) {
                h[0] = __floats2half2_rn(a[0]*dv, a[1]*dv);
                h[1] = __floats2half2_rn(a[2]*dv, a[3]*dv);
                h[2] = __floats2half2_rn(a[4]*dv, a[5]*dv);
                h[3] = __floats2half2_rn(a[6]*dv, a[7]*dv);
            } else {
                h[0] = __floats2half2_rn(a[8]*dv,  a[9]*dv);
                h[1] = __floats2half2_rn(a[10]*dv, 0.0f);
                h[2] = __floats2half2_rn(0.0f, 0.0f);
                h[3] = h[2];
            }
            dst[i] = *(const uint4*)h;
        }
    }
}

// ---- CSR fill: bump rowptr in place; after this rowptr[i] = end(node i) ----
__global__ void fill_kernel(const int* __restrict__ ei) {
    int q = blockIdx.x * blockDim.x + threadIdx.x;
    if (q >= N_EDGES / 4) return;
    int4 rr = ((const int4*)ei)[q];
    int4 cc = ((const int4*)(ei + N_EDGES))[q];
    #pragma unroll
    for (int k = 0; k < 4; k++) {
        int r = (k == 0) ? rr.x : (k == 1) ? rr.y : (k == 2) ? rr.z : rr.w;
        int c = (k == 0) ? cc.x : (k == 1) ? cc.y : (k == 2) ? cc.z : cc.w;
        if ((unsigned)c < N_NODES) {
            int pos = atomicAdd(&g_rowptr[c], 1);
            if ((unsigned)pos < N_EDGES) g_srcs[pos] = r;
        }
    }
}

// ---- fused CSR-gather(fp16 rows) + transform(f32x2) + ReLU + pool ----
__global__ void __launch_bounds__(256)
fused_kernel(const float* __restrict__ Wc, const float* __restrict__ bc) {
    int b     = blockIdx.x >> 4;      // SPLIT=16
    int split = blockIdx.x & 15;
    int start = g_bnd[b];
    int end   = g_bnd[b + 1];
    int total = end - start;
    int chunk = (total + SPLIT - 1) / SPLIT;
    int s0    = start + split * chunk;
    int s1    = min(s0 + chunk, end);

    __shared__ float sW[N_FEAT * HIDDEN];
    __shared__ float sb[HIDDEN];
    __shared__ __align__(16) float sxT[N_FEAT][TILE];   // feature-major tile (fp32)
    __shared__ float red[4][HIDDEN];

    for (int i = threadIdx.x; i < N_FEAT * HIDDEN; i += blockDim.x) sW[i] = Wc[i];
    if (threadIdx.x < HIDDEN) sb[threadIdx.x] = bc[threadIdx.x];
    __syncthreads();

    int j = threadIdx.x & 63;
    int s = threadIdx.x >> 6;

    ull w2[N_FEAT];
    #pragma unroll
    for (int f = 0; f < N_FEAT; f++) { float w = sW[f * HIDDEN + j]; w2[f] = pack2(w, w); }
    float bj  = sb[j];
    ull   bj2 = pack2(bj, bj);
    float acc = 0.0f;
    int   padsum = 0;

    for (int t0 = s0; t0 < s1; t0 += TILE) {
        int cnt  = min(TILE, s1 - t0);
        int cntp = (cnt + 3) & ~3;
        __syncthreads();
        // Phase A: gather + aggregate, one node per thread; 2 LDG.128 per edge
        if (threadIdx.x < cntp) {
            float a[N_FEAT + 1];
            #pragma unroll
            for (int f = 0; f <= N_FEAT; f++) a[f] = 0.0f;
            if (threadIdx.x < cnt) {
                int node = t0 + threadIdx.x;
                int beg = (node > 0) ? g_rowptr[node - 1] : 0;
                int fin = g_rowptr[node];
                for (int e = beg; e < fin; e++) {
                    int src = g_srcs[e];
                    if ((unsigned)src < N_NODES) {
                        const uint4* ur = (const uint4*)&g_xpad[src * HPAD];
                        uint4 p0 = ur[0], p1 = ur[1];
                        const __half2* h0 = (const __half2*)&p0;
                        const __half2* h1 = (const __half2*)&p1;
                        #pragma unroll
                        for (int m = 0; m < 4; m++) {
                            float2 f0 = __half22float2(h0[m]);
                            a[m*2+0] += f0.x; a[m*2+1] += f0.y;
                        }
                        float2 f4 = __half22float2(h1[0]);
                        a[8] += f4.x; a[9] += f4.y;
                        float2 f5 = __half22float2(h1[1]);
                        a[10] += f5.x;
                    }
                }
                float dv = g_dinv[node];
                #pragma unroll
                for (int f = 0; f < N_FEAT; f++) a[f] *= dv;
            }
            #pragma unroll
            for (int f = 0; f < N_FEAT; f++) sxT[f][threadIdx.x] = a[f];
        }
        __syncthreads();
        // Phase B: packed f32x2 transform, 4 nodes per iteration
        for (int n0 = s * 4; n0 < cntp; n0 += 16) {
            ull d0 = bj2, d1 = bj2;
            #pragma unroll
            for (int f = 0; f < N_FEAT; f++) {
                ulonglong2 v = *(const ulonglong2*)&sxT[f][n0];
                d0 = fma2(v.x, w2[f], d0);
                d1 = fma2(v.y, w2[f], d1);
            }
            float h0, h1, h2, h3;
            unpack2(h0, h1, d0);
            unpack2(h2, h3, d1);
            acc += fmaxf(h0, 0.0f) + fmaxf(h1, 0.0f) + fmaxf(h2, 0.0f) + fmaxf(h3, 0.0f);
        }
        int padc = cntp - cnt;
        if (padc && (((cnt >> 2) & 3) == s)) padsum += padc;
    }

    acc -= (float)padsum * fmaxf(bj, 0.0f);

    red[s][j] = acc;
    __syncthreads();
    if (s == 0) {
        float tot = red[0][j] + red[1][j] + red[2][j] + red[3][j];
        atomicAdd(&g_pooled[b * HIDDEN + j], tot);
    }
}

// ---- out[b][c] = (pooled[b]/max(cnt,1)) @ W_lin + b_lin ----
__global__ void final_kernel(const float* __restrict__ Wlin,
                             const float* __restrict__ blin,
                             float* __restrict__ out) {
    int t = blockIdx.x * blockDim.x + threadIdx.x;
    if (t < BATCH * N_CLASSES) {
        int b = t / N_CLASSES, c = t % N_CLASSES;
        int cnt   = g_bnd[b + 1] - g_bnd[b];
        float inv = 1.0f / fmaxf((float)cnt, 1.0f);
        float acc = blin[c];
        #pragma unroll 8
        for (int jj = 0; jj < HIDDEN; jj++)
            acc = fmaf(g_pooled[b * HIDDEN + jj] * inv, Wlin[jj * N_CLASSES + c], acc);
        out[t] = acc;
    }
}

extern "C" void kernel_launch(void* const* d_in, const int* in_sizes, int n_in,
                              void* d_out, int out_size) {
    const float* x     = (const float*)d_in[0];
    const int*   ei    = (const int*)d_in[1];     // int64 narrowed to int32 by harness
    const int*   batch = (const int*)d_in[3];
    const float* Wc    = (const float*)d_in[4];
    const float* bc    = (const float*)d_in[5];
    const float* Wlin  = (const float*)d_in[6];
    const float* blin  = (const float*)d_in[7];
    float*       out   = (float*)d_out;

    static void* p_count  = nullptr;
    static void* p_pooled = nullptr;
    if (!p_count) {
        cudaGetSymbolAddress(&p_count,  g_count);
        cudaGetSymbolAddress(&p_pooled, g_pooled);
    }

    cudaMemsetAsync(p_count,  0, sizeof(int)   * N_NODES);
    cudaMemsetAsync(p_pooled, 0, sizeof(float) * BATCH * HIDDEN);

    hist_bnd_kernel<<<(N_EDGES / 4 + 255) / 256, 256>>>(ei, batch);
    scan1_kernel<<<NB_SCAN, 256>>>();
    scan2_kernel<<<1, 256>>>();
    finish_kernel<<<(N_NODES + FIN_NODES - 1) / FIN_NODES, 256>>>(x);
    fill_kernel<<<(N_EDGES / 4 + 255) / 256, 256>>>(ei);
    fused_kernel<<<BATCH * SPLIT, 256>>>(Wc, bc);
    final_kernel<<<(BATCH * N_CLASSES + 127) / 128, 128>>>(Wlin, blin, out);
}

// round 15
// speedup vs baseline: 1.3718x; 1.0300x over previous
#include <cuda_runtime.h>
#include <cuda_fp16.h>

#define N_NODES   1000000
#define N_EDGES   2000000
#define N_FEAT    11
#define HPAD      16           // fp16 halves per padded u row (32 bytes)
#define HIDDEN    64
#define N_CLASSES 19
#define BATCH     128

#define SPLIT 16
#define TILE  256
#define NB_SCAN 977            // ceil(1M / 1024)
#define FIN_NODES 256

// ---- scratch (device globals; no allocs) ----
__device__ __align__(16) int    g_count[N_NODES];
__device__ __align__(16) int    g_rowptr[N_NODES + 4];   // after fill: rowptr[i] = end of node i
__device__ __align__(16) int    g_srcs[N_EDGES];
__device__ __align__(16) float  g_dinv[N_NODES];
__device__ __align__(16) __half g_xpad[N_NODES * HPAD];  // u = x * dinv[row], fp16, 32B rows
__device__ float g_pooled[BATCH * HIDDEN];
__device__ int   g_bnd[BATCH + 1];
__device__ int   g_bsum[1024];
__device__ int   g_boffs[1024];

typedef unsigned long long ull;
__device__ __forceinline__ ull fma2(ull a, ull b, ull c) {
    ull d; asm("fma.rn.f32x2 %0, %1, %2, %3;" : "=l"(d) : "l"(a), "l"(b), "l"(c)); return d;
}
__device__ __forceinline__ ull pack2(float lo, float hi) {
    ull d; asm("mov.b64 %0, {%1, %2};" : "=l"(d) : "f"(lo), "f"(hi)); return d;
}
__device__ __forceinline__ void unpack2(float& lo, float& hi, ull v) {
    asm("mov.b64 {%0, %1}, %2;" : "=f"(lo), "=f"(hi) : "l"(v));
}

// ---- fused histogram (in-degree) + batch segment boundaries ----
__global__ void hist_bnd_kernel(const int* __restrict__ ei,
                                const int* __restrict__ batch) {
    int q = blockIdx.x * blockDim.x + threadIdx.x;
    if (q < N_EDGES / 4) {
        int4 cc = ((const int4*)(ei + N_EDGES))[q];
        if ((unsigned)cc.x < N_NODES) atomicAdd(&g_count[cc.x], 1);
        if ((unsigned)cc.y < N_NODES) atomicAdd(&g_count[cc.y], 1);
        if ((unsigned)cc.z < N_NODES) atomicAdd(&g_count[cc.z], 1);
        if ((unsigned)cc.w < N_NODES) atomicAdd(&g_count[cc.w], 1);
    }
    if (q < N_NODES / 4) {
        int i0 = q * 4;
        int4 v = ((const int4*)batch)[q];
        int prev = (i0 == 0) ? -1 : batch[i0 - 1];
        int vals[4] = {v.x, v.y, v.z, v.w};
        #pragma unroll
        for (int t = 0; t < 4; t++) {
            int cur = vals[t];
            for (int k = prev + 1; k <= cur && k <= BATCH; k++) g_bnd[k] = i0 + t;
            prev = cur;
        }
        if (i0 + 4 == N_NODES) {
            for (int k = prev + 1; k <= BATCH; k++) g_bnd[k] = N_NODES;
        }
    }
}

// ---- shfl-based block scan: 256 threads x 4 elems = 1024/block ----
__global__ void scan1_kernel() {
    int tid = threadIdx.x, lane = tid & 31, wid = tid >> 5;
    int idx4 = blockIdx.x * 256 + tid;
    int4 v = (idx4 * 4 < N_NODES) ? ((const int4*)g_count)[idx4] : make_int4(0,0,0,0);
    int s = v.x + v.y + v.z + v.w;
    int incl = s;
    #pragma unroll
    for (int o = 1; o < 32; o <<= 1) {
        int t = __shfl_up_sync(0xffffffffu, incl, o);
        if (lane >= o) incl += t;
    }
    __shared__ int wsum[8];
    if (lane == 31) wsum[wid] = incl;
    __syncthreads();
    int woff = 0;
    #pragma unroll
    for (int w = 0; w < 8; w++) if (w < wid) woff += wsum[w];
    int excl = woff + incl - s;
    if (idx4 * 4 < N_NODES) {
        int4 r;
        r.x = excl; r.y = excl + v.x; r.z = r.y + v.y; r.w = r.z + v.z;
        ((int4*)g_rowptr)[idx4] = r;
    }
    if (tid == 255) g_bsum[blockIdx.x] = woff + incl;
}

__global__ void scan2_kernel() {
    int tid = threadIdx.x, lane = tid & 31, wid = tid >> 5;
    int i0 = tid * 4;
    int v[4];
    #pragma unroll
    for (int k = 0; k < 4; k++) v[k] = (i0 + k < NB_SCAN) ? g_bsum[i0 + k] : 0;
    int s = v[0] + v[1] + v[2] + v[3];
    int incl = s;
    #pragma unroll
    for (int o = 1; o < 32; o <<= 1) {
        int t = __shfl_up_sync(0xffffffffu, incl, o);
        if (lane >= o) incl += t;
    }
    __shared__ int wsum[8];
    if (lane == 31) wsum[wid] = incl;
    __syncthreads();
    int woff = 0;
    #pragma unroll
    for (int w = 0; w < 8; w++) if (w < wid) woff += wsum[w];
    int excl = woff + incl - s;
    #pragma unroll
    for (int k = 0; k < 4; k++) {
        if (i0 + k < NB_SCAN) g_boffs[i0 + k] = excl;
        excl += v[k];
    }
}

// ---- tiny: rowptr += per-1024-block offsets ----
__global__ void rowptr_fix_kernel() {
    int q = blockIdx.x * blockDim.x + threadIdx.x;
    if (q >= N_NODES / 4) return;
    int off = g_boffs[q >> 8];
    int4 rp = ((const int4*)g_rowptr)[q];
    rp.x += off; rp.y += off; rp.z += off; rp.w += off;
    ((int4*)g_rowptr)[q] = rp;
}

// ---- dinv + fp16 pad (u = x * dinv); needs only g_count ----
__global__ void __launch_bounds__(256)
dinv_pad_kernel(const float* __restrict__ x) {
    __shared__ float sx[FIN_NODES * N_FEAT];   // 11 KB
    __shared__ float sdv[FIN_NODES];
    int base = blockIdx.x * FIN_NODES;
    int cnt  = min(FIN_NODES, N_NODES - base);
    int tid  = threadIdx.x;

    // 1) coalesced x slab load
    {
        const float4* xs = (const float4*)(x + (long long)base * N_FEAT);
        float4* s4 = (float4*)sx;
        int nv = cnt * N_FEAT / 4;
        for (int i = tid; i < nv; i += FIN_NODES) s4[i] = xs[i];
    }
    // 2) count -> dinv
    if (tid < cnt / 4) {
        int q = base / 4 + tid;
        int4 c4 = ((const int4*)g_count)[q];
        float4 dv;
        dv.x = (c4.x > 0) ? rsqrtf((float)c4.x) : 0.0f;
        dv.y = (c4.y > 0) ? rsqrtf((float)c4.y) : 0.0f;
        dv.z = (c4.z > 0) ? rsqrtf((float)c4.z) : 0.0f;
        dv.w = (c4.w > 0) ? rsqrtf((float)c4.w) : 0.0f;
        ((float4*)g_dinv)[q] = dv;
        *(float4*)&sdv[tid * 4] = dv;
    }
    __syncthreads();
    // 3) coalesced fp16 xpad write: 2 uint4 (8 half2) per node
    {
        uint4* dst = (uint4*)&g_xpad[(long long)base * HPAD];
        int nv = cnt * 2;
        for (int i = tid; i < nv; i += FIN_NODES) {
            int node = i >> 1, hi = i & 1;
            float dv = sdv[node];
            const float* a = &sx[node * N_FEAT];
            __half2 h[4];
            if (hi == 0) {
                h[0] = __floats2half2_rn(a[0]*dv, a[1]*dv);
                h[1] = __floats2half2_rn(a[2]*dv, a[3]*dv);
                h[2] = __floats2half2_rn(a[4]*dv, a[5]*dv);
                h[3] = __floats2half2_rn(a[6]*dv, a[7]*dv);
            } else {
                h[0] = __floats2half2_rn(a[8]*dv,  a[9]*dv);
                h[1] = __floats2half2_rn(a[10]*dv, 0.0f);
                h[2] = __floats2half2_rn(0.0f, 0.0f);
                h[3] = h[2];
            }
            dst[i] = *(const uint4*)h;
        }
    }
}

// ---- CSR fill: bump rowptr in place; after this rowptr[i] = end(node i) ----
__global__ void fill_kernel(const int* __restrict__ ei) {
    int q = blockIdx.x * blockDim.x + threadIdx.x;
    if (q >= N_EDGES / 4) return;
    int4 rr = ((const int4*)ei)[q];
    int4 cc = ((const int4*)(ei + N_EDGES))[q];
    #pragma unroll
    for (int k = 0; k < 4; k++) {
        int r = (k == 0) ? rr.x : (k == 1) ? rr.y : (k == 2) ? rr.z : rr.w;
        int c = (k == 0) ? cc.x : (k == 1) ? cc.y : (k == 2) ? cc.z : cc.w;
        if ((unsigned)c < N_NODES) {
            int pos = atomicAdd(&g_rowptr[c], 1);
            if ((unsigned)pos < N_EDGES) g_srcs[pos] = r;
        }
    }
}

// ---- fused CSR-gather(fp16 rows) + transform(f32x2) + ReLU + pool ----
__global__ void __launch_bounds__(256)
fused_kernel(const float* __restrict__ Wc, const float* __restrict__ bc) {
    int b     = blockIdx.x >> 4;      // SPLIT=16
    int split = blockIdx.x & 15;
    int start = g_bnd[b];
    int end   = g_bnd[b + 1];
    int total = end - start;
    int chunk = (total + SPLIT - 1) / SPLIT;
    int s0    = start + split * chunk;
    int s1    = min(s0 + chunk, end);

    __shared__ float sW[N_FEAT * HIDDEN];
    __shared__ float sb[HIDDEN];
    __shared__ __align__(16) float sxT[N_FEAT][TILE];   // feature-major tile (fp32)
    __shared__ float red[4][HIDDEN];

    for (int i = threadIdx.x; i < N_FEAT * HIDDEN; i += blockDim.x) sW[i] = Wc[i];
    if (threadIdx.x < HIDDEN) sb[threadIdx.x] = bc[threadIdx.x];
    __syncthreads();

    int j = threadIdx.x & 63;
    int s = threadIdx.x >> 6;

    ull w2[N_FEAT];
    #pragma unroll
    for (int f = 0; f < N_FEAT; f++) { float w = sW[f * HIDDEN + j]; w2[f] = pack2(w, w); }
    float bj  = sb[j];
    ull   bj2 = pack2(bj, bj);
    float acc = 0.0f;
    int   padsum = 0;

    for (int t0 = s0; t0 < s1; t0 += TILE) {
        int cnt  = min(TILE, s1 - t0);
        int cntp = (cnt + 3) & ~3;
        __syncthreads();
        // Phase A: gather + aggregate, one node per thread; 2 LDG.128 per edge
        if (threadIdx.x < cntp) {
            float a[N_FEAT + 1];
            #pragma unroll
            for (int f = 0; f <= N_FEAT; f++) a[f] = 0.0f;
            if (threadIdx.x < cnt) {
                int node = t0 + threadIdx.x;
                int beg = (node > 0) ? g_rowptr[node - 1] : 0;
                int fin = g_rowptr[node];
                for (int e = beg; e < fin; e++) {
                    int src = g_srcs[e];
                    if ((unsigned)src < N_NODES) {
                        const uint4* ur = (const uint4*)&g_xpad[src * HPAD];
                        uint4 p0 = ur[0], p1 = ur[1];
                        const __half2* h0 = (const __half2*)&p0;
                        const __half2* h1 = (const __half2*)&p1;
                        #pragma unroll
                        for (int m = 0; m < 4; m++) {
                            float2 f0 = __half22float2(h0[m]);
                            a[m*2+0] += f0.x; a[m*2+1] += f0.y;
                        }
                        float2 f4 = __half22float2(h1[0]);
                        a[8] += f4.x; a[9] += f4.y;
                        float2 f5 = __half22float2(h1[1]);
                        a[10] += f5.x;
                    }
                }
                float dv = g_dinv[node];
                #pragma unroll
                for (int f = 0; f < N_FEAT; f++) a[f] *= dv;
            }
            #pragma unroll
            for (int f = 0; f < N_FEAT; f++) sxT[f][threadIdx.x] = a[f];
        }
        __syncthreads();
        // Phase B: packed f32x2 transform, 4 nodes per iteration
        for (int n0 = s * 4; n0 < cntp; n0 += 16) {
            ull d0 = bj2, d1 = bj2;
            #pragma unroll
            for (int f = 0; f < N_FEAT; f++) {
                ulonglong2 v = *(const ulonglong2*)&sxT[f][n0];
                d0 = fma2(v.x, w2[f], d0);
                d1 = fma2(v.y, w2[f], d1);
            }
            float h0, h1, h2, h3;
            unpack2(h0, h1, d0);
            unpack2(h2, h3, d1);
            acc += fmaxf(h0, 0.0f) + fmaxf(h1, 0.0f) + fmaxf(h2, 0.0f) + fmaxf(h3, 0.0f);
        }
        int padc = cntp - cnt;
        if (padc && (((cnt >> 2) & 3) == s)) padsum += padc;
    }

    acc -= (float)padsum * fmaxf(bj, 0.0f);

    red[s][j] = acc;
    __syncthreads();
    if (s == 0) {
        float tot = red[0][j] + red[1][j] + red[2][j] + red[3][j];
        atomicAdd(&g_pooled[b * HIDDEN + j], tot);
    }
}

// ---- out[b][c] = (pooled[b]/max(cnt,1)) @ W_lin + b_lin ----
__global__ void final_kernel(const float* __restrict__ Wlin,
                             const float* __restrict__ blin,
                             float* __restrict__ out) {
    int t = blockIdx.x * blockDim.x + threadIdx.x;
    if (t < BATCH * N_CLASSES) {
        int b = t / N_CLASSES, c = t % N_CLASSES;
        int cnt   = g_bnd[b + 1] - g_bnd[b];
        float inv = 1.0f / fmaxf((float)cnt, 1.0f);
        float acc = blin[c];
        #pragma unroll 8
        for (int jj = 0; jj < HIDDEN; jj++)
            acc = fmaf(g_pooled[b * HIDDEN + jj] * inv, Wlin[jj * N_CLASSES + c], acc);
        out[t] = acc;
    }
}

extern "C" void kernel_launch(void* const* d_in, const int* in_sizes, int n_in,
                              void* d_out, int out_size) {
    const float* x     = (const float*)d_in[0];
    const int*   ei    = (const int*)d_in[1];     // int64 narrowed to int32 by harness
    const int*   batch = (const int*)d_in[3];
    const float* Wc    = (const float*)d_in[4];
    const float* bc    = (const float*)d_in[5];
    const float* Wlin  = (const float*)d_in[6];
    const float* blin  = (const float*)d_in[7];
    float*       out   = (float*)d_out;

    static void* p_count  = nullptr;
    static void* p_pooled = nullptr;
    static cudaStream_t s2 = nullptr;
    static cudaEvent_t  ev_fork = nullptr, ev_join = nullptr;
    if (!p_count) {
        cudaGetSymbolAddress(&p_count,  g_count);
        cudaGetSymbolAddress(&p_pooled, g_pooled);
        cudaStreamCreateWithFlags(&s2, cudaStreamNonBlocking);
        cudaEventCreateWithFlags(&ev_fork, cudaEventDisableTiming);
        cudaEventCreateWithFlags(&ev_join, cudaEventDisableTiming);
    }

    // main stream: count memset -> hist
    cudaMemsetAsync(p_count, 0, sizeof(int) * N_NODES);
    hist_bnd_kernel<<<(N_EDGES / 4 + 255) / 256, 256>>>(ei, batch);

    // fork: side stream does pooled memset + dinv/xpad (depends only on counts)
    cudaEventRecord(ev_fork, 0);
    cudaStreamWaitEvent(s2, ev_fork, 0);
    cudaMemsetAsync(p_pooled, 0, sizeof(float) * BATCH * HIDDEN, s2);
    dinv_pad_kernel<<<(N_NODES + FIN_NODES - 1) / FIN_NODES, 256, 0, s2>>>(x);
    cudaEventRecord(ev_join, s2);

    // main stream: scans -> rowptr fix -> CSR fill (runs concurrent with dinv_pad)
    scan1_kernel<<<NB_SCAN, 256>>>();
    scan2_kernel<<<1, 256>>>();
    rowptr_fix_kernel<<<(N_NODES / 4 + 255) / 256, 256>>>();
    fill_kernel<<<(N_EDGES / 4 + 255) / 256, 256>>>(ei);

    // join, then fused + final
    cudaStreamWaitEvent(0, ev_join, 0);
    fused_kernel<<<BATCH * SPLIT, 256>>>(Wc, bc);
    final_kernel<<<(BATCH * N_CLASSES + 127) / 128, 128>>>(Wlin, blin, out);
}